// round 14
// baseline (speedup 1.0000x reference)
#include <cuda_runtime.h>
#include <cuda_bf16.h>
#include <math.h>
#include <stdint.h>

// Problem constants
#define BB 4
#define TT 2048
#define CC 1024
#define HH 16
#define DD 64
#define MM (BB * TT)         // 8192
#define N_QKV (3 * CC)       // 3072
#define ATTN_SCALE 0.12f
#define RMS_EPS 1e-6f
#define LOG2E 1.4426950408889634f

// ---------------- device scratch (allocation-free) ----------------
__device__ float g_qkv[(size_t)MM * N_QKV];          // (M, 3C)
__device__ __nv_bfloat16 g_xh[(size_t)MM * CC],     g_xl[(size_t)MM * CC];
__device__ __nv_bfloat16 g_wh[(size_t)N_QKV * CC],  g_wl[(size_t)N_QKV * CC];
__device__ __nv_bfloat16 g_yh[(size_t)MM * CC],     g_yl[(size_t)MM * CC];
__device__ __nv_bfloat16 g_ph[(size_t)CC * CC],     g_pl[(size_t)CC * CC];
#define AHD ((size_t)BB * HH * TT * DD)
__device__ __nv_bfloat16 g_qh[AHD], g_ql[AHD];
__device__ __nv_bfloat16 g_kh[AHD], g_kl[AHD];
__device__ __nv_bfloat16 g_vth[AHD], g_vtl[AHD];

// =================================================================
// common helpers
// =================================================================
__device__ __forceinline__ uint32_t smem_u32(const void* p) {
    uint32_t a;
    asm("{ .reg .u64 t; cvta.to.shared.u64 t, %1; cvt.u32.u64 %0, t; }"
        : "=r"(a) : "l"(p));
    return a;
}

__device__ __forceinline__ void mma16816(float* d, const uint32_t* a, const uint32_t* b) {
    asm volatile(
        "mma.sync.aligned.m16n8k16.row.col.f32.bf16.bf16.f32 "
        "{%0,%1,%2,%3}, {%4,%5,%6,%7}, {%8,%9}, {%0,%1,%2,%3};"
        : "+f"(d[0]), "+f"(d[1]), "+f"(d[2]), "+f"(d[3])
        : "r"(a[0]), "r"(a[1]), "r"(a[2]), "r"(a[3]), "r"(b[0]), "r"(b[1]));
}

#define LDSM_X4(r, addr) \
    asm volatile("ldmatrix.sync.aligned.m8n8.x4.shared.b16 {%0,%1,%2,%3}, [%4];" \
                 : "=r"((r)[0]), "=r"((r)[1]), "=r"((r)[2]), "=r"((r)[3]) : "r"(addr))

#define CP_ASYNC(dst, src) \
    asm volatile("cp.async.cg.shared.global [%0], [%1], 16;" \
                 :: "r"(dst), "l"(src) : "memory")
#define CP_COMMIT() asm volatile("cp.async.commit_group;" ::: "memory")
#define CP_WAIT1()  asm volatile("cp.async.wait_group 1;" ::: "memory")

__device__ __forceinline__ uint32_t pack_bf16(float a, float b) {
    __nv_bfloat16 ha = __float2bfloat16(a);
    __nv_bfloat16 hb = __float2bfloat16(b);
    return (uint32_t)__bfloat16_as_ushort(ha) |
           ((uint32_t)__bfloat16_as_ushort(hb) << 16);
}

__device__ __forceinline__ float ex2f(float x) {
    float y;
    asm("ex2.approx.f32 %0, %1;" : "=f"(y) : "f"(x));
    return y;
}

// =================================================================
// split3: one launch splits x, qkv_w, c_proj_w fp32 -> bf16 hi/lo
// =================================================================
__device__ __forceinline__ void split4(const float* __restrict__ in, int i,
                                       __nv_bfloat16* __restrict__ hi,
                                       __nv_bfloat16* __restrict__ lo)
{
    float4 f4 = *(const float4*)(in + i);
    float f[4] = {f4.x, f4.y, f4.z, f4.w};
    uint16_t h[4], l[4];
#pragma unroll
    for (int j = 0; j < 4; j++) {
        __nv_bfloat16 hb = __float2bfloat16(f[j]);
        __nv_bfloat16 lb = __float2bfloat16(f[j] - __bfloat162float(hb));
        h[j] = __bfloat16_as_ushort(hb);
        l[j] = __bfloat16_as_ushort(lb);
    }
    *(uint2*)(hi + i) = make_uint2((uint32_t)h[0] | ((uint32_t)h[1] << 16),
                                   (uint32_t)h[2] | ((uint32_t)h[3] << 16));
    *(uint2*)(lo + i) = make_uint2((uint32_t)l[0] | ((uint32_t)l[1] << 16),
                                   (uint32_t)l[2] | ((uint32_t)l[3] << 16));
}

#define N_X (MM * CC)
#define N_W (N_QKV * CC)
#define N_P (CC * CC)

__global__ __launch_bounds__(256)
void split3(const float* __restrict__ x,
            __nv_bfloat16* __restrict__ xh, __nv_bfloat16* __restrict__ xl,
            const float* __restrict__ w,
            __nv_bfloat16* __restrict__ wh, __nv_bfloat16* __restrict__ wl,
            const float* __restrict__ p,
            __nv_bfloat16* __restrict__ ph, __nv_bfloat16* __restrict__ pl)
{
    const int i = (blockIdx.x * 256 + threadIdx.x) * 4;
    if (i < N_X) {
        split4(x, i, xh, xl);
    } else if (i < N_X + N_W) {
        split4(w, i - N_X, wh, wl);
    } else {
        split4(p, i - N_X - N_W, ph, pl);
    }
}

// =================================================================
// mma.sync bf16x3 GEMM (pre-split, cp.async double buffer, ldmatrix;
// B fragments fetched with x4 ldmatrix). Unchanged from R11 winner.
// =================================================================
#define SROW 20
#define ARR_W (128 * SROW)
#define BUF_W (4 * ARR_W)
#define GEMM_SMEM (2 * BUF_W * 4)

__global__ __launch_bounds__(256, 2)
void mma_gemm_pre(const __nv_bfloat16* __restrict__ Ahg,
                  const __nv_bfloat16* __restrict__ Alg,
                  const __nv_bfloat16* __restrict__ Bhg,
                  const __nv_bfloat16* __restrict__ Blg,
                  float* __restrict__ C, int M, int N, int K)
{
    extern __shared__ uint32_t sw[];
    const uint32_t sbase = smem_u32(sw);

    const int tid = threadIdx.x;
    const int wid = tid >> 5;
    const int lane = tid & 31;
    const int g = lane >> 2;
    const int tig = lane & 3;
    const int wm = (wid & 1) * 64;
    const int wn = (wid >> 1) * 32;

    const int bm = blockIdx.y * 128;
    const int bn = blockIdx.x * 128;

    const int s0 = tid * 2;
    const int lrow0 = s0 >> 2, lseg0 = s0 & 3;
    const int lrow1 = (s0 + 1) >> 2, lseg1 = (s0 + 1) & 3;

    const uint32_t a16 = ((uint32_t)((wm + (lane & 15)) * SROW + (lane >> 4) * 4)) * 4;
    const uint32_t b8q = ((uint32_t)((wn + ((lane >> 4) << 3) + (lane & 7)) * SROW +
                                     ((lane >> 3) & 1) * 4)) * 4;

    float acc[4][4][4];
#pragma unroll
    for (int mt = 0; mt < 4; mt++)
#pragma unroll
        for (int nt = 0; nt < 4; nt++)
#pragma unroll
            for (int r = 0; r < 4; r++) acc[mt][nt][r] = 0.0f;

    const int nch = K >> 5;

    auto issue = [&](int ci, int buf) {
        const int kc = ci << 5;
        const uint32_t bb = sbase + buf * (BUF_W * 4);
#pragma unroll
        for (int j = 0; j < 2; j++) {
            const int row = j ? lrow1 : lrow0;
            const int seg = j ? lseg1 : lseg0;
            const size_t goff = (size_t)(bm + row) * K + kc + seg * 8;
            const size_t goffB = (size_t)(bn + row) * K + kc + seg * 8;
            const uint32_t soff = (row * SROW + seg * 4) * 4;
            CP_ASYNC(bb + 0 * ARR_W * 4 + soff, Ahg + goff);
            CP_ASYNC(bb + 1 * ARR_W * 4 + soff, Alg + goff);
            CP_ASYNC(bb + 2 * ARR_W * 4 + soff, Bhg + goffB);
            CP_ASYNC(bb + 3 * ARR_W * 4 + soff, Blg + goffB);
        }
    };

    issue(0, 0); CP_COMMIT();
    issue(1, 1); CP_COMMIT();

    for (int ci = 0; ci < nch; ci++) {
        const int buf = ci & 1;
        CP_WAIT1();
        __syncthreads();

        const uint32_t Ah_b = sbase + buf * (BUF_W * 4);
        const uint32_t Al_b = Ah_b + ARR_W * 4;
        const uint32_t Bh_b = Ah_b + 2 * ARR_W * 4;
        const uint32_t Bl_b = Ah_b + 3 * ARR_W * 4;

#pragma unroll
        for (int ks = 0; ks < 2; ks++) {
            const uint32_t kwb = ks * 32;
            uint32_t bhf[4][2], blf[4][2];
#pragma unroll
            for (int ntp = 0; ntp < 2; ntp++) {
                uint32_t q[4];
                LDSM_X4(q, Bh_b + b8q + ntp * (16 * SROW * 4) + kwb);
                bhf[2 * ntp][0] = q[0]; bhf[2 * ntp][1] = q[1];
                bhf[2 * ntp + 1][0] = q[2]; bhf[2 * ntp + 1][1] = q[3];
                LDSM_X4(q, Bl_b + b8q + ntp * (16 * SROW * 4) + kwb);
                blf[2 * ntp][0] = q[0]; blf[2 * ntp][1] = q[1];
                blf[2 * ntp + 1][0] = q[2]; blf[2 * ntp + 1][1] = q[3];
            }
#pragma unroll
            for (int mt = 0; mt < 4; mt++) {
                uint32_t ah[4], al[4];
                LDSM_X4(ah, Ah_b + a16 + mt * (16 * SROW * 4) + kwb);
                LDSM_X4(al, Al_b + a16 + mt * (16 * SROW * 4) + kwb);
#pragma unroll
                for (int nt = 0; nt < 4; nt++) {
                    mma16816(acc[mt][nt], ah, bhf[nt]);
                    mma16816(acc[mt][nt], ah, blf[nt]);
                    mma16816(acc[mt][nt], al, bhf[nt]);
                }
            }
        }
        __syncthreads();
        if (ci + 2 < nch) issue(ci + 2, buf);
        CP_COMMIT();
    }

#pragma unroll
    for (int mt = 0; mt < 4; mt++) {
        const int r0 = bm + wm + mt * 16 + g;
#pragma unroll
        for (int nt = 0; nt < 4; nt++) {
            const int col = bn + wn + nt * 8 + tig * 2;
            *(float2*)&C[(size_t)r0 * N + col] =
                make_float2(acc[mt][nt][0], acc[mt][nt][1]);
            *(float2*)&C[(size_t)(r0 + 8) * N + col] =
                make_float2(acc[mt][nt][2], acc[mt][nt][3]);
        }
    }
}

// =================================================================
// Fused post-process + V transpose.
// Grid (TT/64, B*H), 256 threads. Block handles 64 t-rows of one head.
// Thread (tr = tid>>2, tig = tid&3) owns row t=tr, d = tig*16..+15.
// rmsnorm reduces across the tig group; rotary pairs tig0<->tig2,
// tig1<->tig3 (upper 16 freqs are identity). V is staged in smem
// [t][d] and written out d-major (B*H, D, T) coalesced.
// =================================================================
__global__ __launch_bounds__(256)
void postproc_fused(const float* __restrict__ qkv, const float* __restrict__ ve,
                    const float* __restrict__ lambdas,
                    __nv_bfloat16* __restrict__ qh, __nv_bfloat16* __restrict__ ql,
                    __nv_bfloat16* __restrict__ kh, __nv_bfloat16* __restrict__ kl,
                    __nv_bfloat16* __restrict__ vth, __nv_bfloat16* __restrict__ vtl)
{
    __shared__ uint16_t svh[64][65], svl[64][65];

    const int tid = threadIdx.x;
    const int bh = blockIdx.y;
    const int tb = blockIdx.x;
    const int b = bh >> 4;
    const int h = bh & 15;
    const int tr = tid >> 2;
    const int tig = tid & 3;
    const int d0 = tig * 16;
    const int t = tb * 64 + tr;
    const int m = b * TT + t;

    const float* row = qkv + (size_t)m * N_QKV + h * DD;
    const float* verow = ve + (size_t)m * CC + h * DD;
    const float lam0 = lambdas[0], lam1 = lambdas[1];

    float q[16], k[16], v[16];
#pragma unroll
    for (int u = 0; u < 4; u++) {
        *(float4*)&q[4 * u] = *(const float4*)(row + d0 + 4 * u);
        *(float4*)&k[4 * u] = *(const float4*)(row + CC + d0 + 4 * u);
        float4 v4 = *(const float4*)(row + 2 * CC + d0 + 4 * u);
        float4 e4 = *(const float4*)(verow + d0 + 4 * u);
        v[4 * u + 0] = lam0 * v4.x + lam1 * e4.x;
        v[4 * u + 1] = lam0 * v4.y + lam1 * e4.y;
        v[4 * u + 2] = lam0 * v4.z + lam1 * e4.z;
        v[4 * u + 3] = lam0 * v4.w + lam1 * e4.w;
    }

    // rmsnorm over 64 d (16 per thread, reduce across tig group)
    float sq = 0.0f, sk = 0.0f;
#pragma unroll
    for (int j = 0; j < 16; j++) { sq += q[j] * q[j]; sk += k[j] * k[j]; }
    sq += __shfl_xor_sync(0xffffffffu, sq, 1);
    sq += __shfl_xor_sync(0xffffffffu, sq, 2);
    sk += __shfl_xor_sync(0xffffffffu, sk, 1);
    sk += __shfl_xor_sync(0xffffffffu, sk, 2);
    const float rq = 1.0f / sqrtf(sq * (1.0f / 64.0f) + RMS_EPS);
    const float rk = 1.0f / sqrtf(sk * (1.0f / 64.0f) + RMS_EPS);
#pragma unroll
    for (int j = 0; j < 16; j++) { q[j] *= rq; k[j] *= rk; }

    // rotary: partner exchange (d <-> d+32) via shfl_xor(2)
    float qp[16], kp[16];
#pragma unroll
    for (int j = 0; j < 16; j++) {
        qp[j] = __shfl_xor_sync(0xffffffffu, q[j], 2);
        kp[j] = __shfl_xor_sync(0xffffffffu, k[j], 2);
    }
    const float qs = ATTN_SCALE * LOG2E;
    const bool lowf = ((tig & 1) == 0);   // these 16 d's have nonzero freqs
    const bool x1side = (tig < 2);
#pragma unroll
    for (int j = 0; j < 16; j++) {
        float c = 1.0f, s = 0.0f;
        if (lowf) {
            const float ang = (float)exp2(-(10.0 / 15.0) * (double)j);
            sincosf((float)t * ang, &s, &c);
        }
        float qn = x1side ? (q[j] * c + qp[j] * s) : (q[j] * c - qp[j] * s);
        float kn = x1side ? (k[j] * c + kp[j] * s) : (k[j] * c - kp[j] * s);
        q[j] = qn * qs;
        k[j] = kn;
    }

    // store q, k bf16 hi/lo (row-major (B*H, T, D))
    {
        const size_t o = ((size_t)bh * TT + t) * DD + d0;
        uint32_t qhw[8], qlw[8], khw[8], klw[8];
#pragma unroll
        for (int j = 0; j < 8; j++) {
            __nv_bfloat16 hb0 = __float2bfloat16(q[2 * j]);
            __nv_bfloat16 hb1 = __float2bfloat16(q[2 * j + 1]);
            qhw[j] = (uint32_t)__bfloat16_as_ushort(hb0) |
                     ((uint32_t)__bfloat16_as_ushort(hb1) << 16);
            qlw[j] = pack_bf16(q[2 * j] - __bfloat162float(hb0),
                               q[2 * j + 1] - __bfloat162float(hb1));
            __nv_bfloat16 kb0 = __float2bfloat16(k[2 * j]);
            __nv_bfloat16 kb1 = __float2bfloat16(k[2 * j + 1]);
            khw[j] = (uint32_t)__bfloat16_as_ushort(kb0) |
                     ((uint32_t)__bfloat16_as_ushort(kb1) << 16);
            klw[j] = pack_bf16(k[2 * j] - __bfloat162float(kb0),
                               k[2 * j + 1] - __bfloat162float(kb1));
        }
        *(uint4*)(qh + o) = make_uint4(qhw[0], qhw[1], qhw[2], qhw[3]);
        *(uint4*)(qh + o + 8) = make_uint4(qhw[4], qhw[5], qhw[6], qhw[7]);
        *(uint4*)(ql + o) = make_uint4(qlw[0], qlw[1], qlw[2], qlw[3]);
        *(uint4*)(ql + o + 8) = make_uint4(qlw[4], qlw[5], qlw[6], qlw[7]);
        *(uint4*)(kh + o) = make_uint4(khw[0], khw[1], khw[2], khw[3]);
        *(uint4*)(kh + o + 8) = make_uint4(khw[4], khw[5], khw[6], khw[7]);
        *(uint4*)(kl + o) = make_uint4(klw[0], klw[1], klw[2], klw[3]);
        *(uint4*)(kl + o + 8) = make_uint4(klw[4], klw[5], klw[6], klw[7]);
    }

    // stage v hi/lo into smem [t][d]
#pragma unroll
    for (int j = 0; j < 16; j++) {
        __nv_bfloat16 hb = __float2bfloat16(v[j]);
        __nv_bfloat16 lb = __float2bfloat16(v[j] - __bfloat162float(hb));
        svh[tr][d0 + j] = __bfloat16_as_ushort(hb);
        svl[tr][d0 + j] = __bfloat16_as_ushort(lb);
    }
    __syncthreads();

    // write V transposed: (B*H, D, T), coalesced along t
    {
        const int r = tid >> 2;          // d index
        const int cs = tig * 16;         // t chunk
        const size_t dst = ((size_t)bh * DD + r) * TT + tb * 64 + cs;
        uint32_t* oh = (uint32_t*)(vth + dst);
        uint32_t* ol = (uint32_t*)(vtl + dst);
#pragma unroll
        for (int j = 0; j < 8; j++) {
            oh[j] = (uint32_t)svh[cs + 2 * j][r] |
                    ((uint32_t)svh[cs + 2 * j + 1][r] << 16);
            ol[j] = (uint32_t)svl[cs + 2 * j][r] |
                    ((uint32_t)svl[cs + 2 * j + 1][r] << 16);
        }
    }
}

// =================================================================
// Tensor-core flash attention (causal, no-max softmax via ex2,
// bf16x3), register-resident P AND register-cached Q fragments.
// BQ=128, BKV=64, 256 threads, 2 CTAs/SM (110.6 KB smem).
// =================================================================
#define FL_SROW 36
#define FLQ_H 0
#define FLQ_L 4608
#define FLKV 9216
#define FL_SMEM (27648 * 4)   // 110592 B

__global__ __launch_bounds__(256, 2)
void flash_mma(const __nv_bfloat16* __restrict__ qh, const __nv_bfloat16* __restrict__ ql,
               const __nv_bfloat16* __restrict__ kh, const __nv_bfloat16* __restrict__ kl,
               const __nv_bfloat16* __restrict__ vth, const __nv_bfloat16* __restrict__ vtl,
               __nv_bfloat16* __restrict__ yh, __nv_bfloat16* __restrict__ yl)
{
    extern __shared__ uint32_t sw[];
    const uint32_t sb = smem_u32(sw);
    const int tid = threadIdx.x;
    const int wid = tid >> 5;
    const int lane = tid & 31;
    const int g = lane >> 2;
    const int tig = lane & 3;
    const int bh = blockIdx.y;
    const int qb = (int)gridDim.x - 1 - (int)blockIdx.x;   // heavy first

    const int wm = wid * 16;    // this warp's 16 rows of the 128-row Q tile

    const uint32_t a16 = ((uint32_t)((lane & 15) * FL_SROW + (lane >> 4) * 4)) * 4;
    const uint32_t b8q = ((uint32_t)((((lane >> 4) << 3) + (lane & 7)) * FL_SROW +
                                     ((lane >> 3) & 1) * 4)) * 4;

    const size_t base = (size_t)bh * TT * DD;

    // ---- Q tile load (cp.async): 2 arrays x 128 rows ----
    {
        const int arr = tid >> 7;
        const int row = tid & 127;
        const __nv_bfloat16* src = (arr ? ql : qh) + base + ((size_t)(qb * 128 + row)) * 64;
        const uint32_t dst = sb + ((arr ? FLQ_L : FLQ_H) + row * FL_SROW) * 4;
#pragma unroll
        for (int s = 0; s < 8; s++) CP_ASYNC(dst + s * 16, src + s * 8);
    }

    // KV loader mapping: 4 arrays x 64 rows
    const int kvarr = tid >> 6;          // 0:Kh 1:Kl 2:Vth 3:Vtl
    const int kvrow = tid & 63;
    const bool kvisV = kvarr >= 2;
    const __nv_bfloat16* kvbase =
        (kvarr == 0) ? (kh + base) : (kvarr == 1) ? (kl + base)
        : (kvarr == 2) ? (vth + base) : (vtl + base);
    const uint32_t kvdst0 = sb + (FLKV + kvarr * 2304 + kvrow * FL_SROW) * 4;

    auto issueKV = [&](int kb, int buf) {
        const __nv_bfloat16* src = kvisV
            ? (kvbase + (size_t)kvrow * TT + kb * 64)
            : (kvbase + ((size_t)(kb * 64 + kvrow)) * 64);
        const uint32_t dst = kvdst0 + buf * 9216 * 4;
#pragma unroll
        for (int s = 0; s < 8; s++) CP_ASYNC(dst + s * 16, src + s * 8);
    };

    const int nkb = 2 * qb + 2;
    issueKV(0, 0); CP_COMMIT();          // group: Q + KV0
    if (nkb > 1) issueKV(1, 1);
    CP_COMMIT();
    CP_WAIT1();                          // Q + KV0 ready
    __syncthreads();

    // ---- cache Q fragments in registers (CTA-invariant) ----
    uint32_t qfh[4][4], qfl[4][4];
#pragma unroll
    for (int ks = 0; ks < 4; ks++) {
        LDSM_X4(qfh[ks], sb + FLQ_H * 4 + a16 + wm * (FL_SROW * 4) + ks * 32);
        LDSM_X4(qfl[ks], sb + FLQ_L * 4 + a16 + wm * (FL_SROW * 4) + ks * 32);
    }

    float O[8][4];
    float lp[2] = {0.0f, 0.0f};
#pragma unroll
    for (int nt = 0; nt < 8; nt++)
#pragma unroll
        for (int r = 0; r < 4; r++) O[nt][r] = 0.0f;

    for (int kb = 0; kb < nkb; kb++) {
        const int buf = kb & 1;
        const uint32_t Khb = sb + (FLKV + buf * 9216) * 4;
        const uint32_t Klb = Khb + 2304 * 4;
        const uint32_t Vhb = Khb + 4608 * 4;
        const uint32_t Vlb = Khb + 6912 * 4;

        // ---- S = Q K^T (bf16x3): 16 rows x 64 cols per warp ----
        float S[8][4];
#pragma unroll
        for (int nt = 0; nt < 8; nt++)
#pragma unroll
            for (int r = 0; r < 4; r++) S[nt][r] = 0.0f;

#pragma unroll
        for (int ks = 0; ks < 4; ks++) {
            const uint32_t kwb = ks * 32;
#pragma unroll
            for (int ntp = 0; ntp < 4; ntp++) {
                uint32_t qk[4], qkl[4];
                LDSM_X4(qk, Khb + b8q + ntp * (16 * FL_SROW * 4) + kwb);
                LDSM_X4(qkl, Klb + b8q + ntp * (16 * FL_SROW * 4) + kwb);
                uint32_t b0[2] = {qk[0], qk[1]}, b1[2] = {qk[2], qk[3]};
                uint32_t c0[2] = {qkl[0], qkl[1]}, c1[2] = {qkl[2], qkl[3]};
                mma16816(S[2 * ntp], qfh[ks], b0);
                mma16816(S[2 * ntp], qfh[ks], c0);
                mma16816(S[2 * ntp], qfl[ks], b0);
                mma16816(S[2 * ntp + 1], qfh[ks], b1);
                mma16816(S[2 * ntp + 1], qfh[ks], c1);
                mma16816(S[2 * ntp + 1], qfl[ks], b1);
            }
        }

        // ---- PV with fused exp2/pack (P built per-ks from live S) ----
        const bool diag = (kb >= 2 * qb);
#pragma unroll
        for (int ks = 0; ks < 4; ks++) {
            const uint32_t kwb = ks * 32;
            uint32_t aph[4], apl[4];
#pragma unroll
            for (int j = 0; j < 2; j++) {
                const int nt = 2 * ks + j;
                const int c0i = kb * 64 + nt * 8 + tig * 2;
#pragma unroll
                for (int h2 = 0; h2 < 2; h2++) {
                    const int grow = qb * 128 + wm + g + h2 * 8;
                    float s0 = S[nt][h2 * 2 + 0];
                    float s1 = S[nt][h2 * 2 + 1];
                    float p0 = (diag && (c0i > grow)) ? 0.0f : ex2f(s0);
                    float p1 = (diag && (c0i + 1 > grow)) ? 0.0f : ex2f(s1);
                    lp[h2] += p0 + p1;
                    __nv_bfloat16 hb0 = __float2bfloat16(p0);
                    __nv_bfloat16 hb1 = __float2bfloat16(p1);
                    aph[j * 2 + h2] = (uint32_t)__bfloat16_as_ushort(hb0) |
                                      ((uint32_t)__bfloat16_as_ushort(hb1) << 16);
                    apl[j * 2 + h2] = pack_bf16(p0 - __bfloat162float(hb0),
                                                p1 - __bfloat162float(hb1));
                }
            }
#pragma unroll
            for (int ntp = 0; ntp < 4; ntp++) {
                uint32_t qv[4], qvl[4];
                LDSM_X4(qv, Vhb + b8q + ntp * (16 * FL_SROW * 4) + kwb);
                LDSM_X4(qvl, Vlb + b8q + ntp * (16 * FL_SROW * 4) + kwb);
                uint32_t b0[2] = {qv[0], qv[1]}, b1[2] = {qv[2], qv[3]};
                uint32_t c0[2] = {qvl[0], qvl[1]}, c1[2] = {qvl[2], qvl[3]};
                mma16816(O[2 * ntp], aph, b0);
                mma16816(O[2 * ntp], aph, c0);
                mma16816(O[2 * ntp], apl, b0);
                mma16816(O[2 * ntp + 1], aph, b1);
                mma16816(O[2 * ntp + 1], aph, c1);
                mma16816(O[2 * ntp + 1], apl, b1);
            }
        }
        __syncthreads();                 // all warps done reading buf
        if (kb + 2 < nkb) issueKV(kb + 2, buf);
        CP_COMMIT();
        CP_WAIT1();                      // tile kb+1 ready
        __syncthreads();
    }

    // ---- row-sum reduce (warp-local) ----
#pragma unroll
    for (int i = 0; i < 2; i++) {
        lp[i] += __shfl_xor_sync(0xffffffffu, lp[i], 1);
        lp[i] += __shfl_xor_sync(0xffffffffu, lp[i], 2);
    }

    // ---- epilogue: O/l -> y bf16 hi/lo, (M, C) layout ----
    const int b = bh >> 4;
    const int h = bh & 15;
#pragma unroll
    for (int h2 = 0; h2 < 2; h2++) {
        const float linv = 1.0f / lp[h2];
        const int t = qb * 128 + wm + g + h2 * 8;
        const size_t rowoff = ((size_t)(b * TT + t)) * CC + h * 64;
#pragma unroll
        for (int nt = 0; nt < 8; nt++) {
            float o0 = O[nt][h2 * 2 + 0] * linv;
            float o1 = O[nt][h2 * 2 + 1] * linv;
            __nv_bfloat16 hb0 = __float2bfloat16(o0);
            __nv_bfloat16 hb1 = __float2bfloat16(o1);
            const size_t col = rowoff + nt * 8 + tig * 2;
            *(uint32_t*)(yh + col) = (uint32_t)__bfloat16_as_ushort(hb0) |
                                     ((uint32_t)__bfloat16_as_ushort(hb1) << 16);
            *(uint32_t*)(yl + col) = pack_bf16(o0 - __bfloat162float(hb0),
                                               o1 - __bfloat162float(hb1));
        }
    }
}

// =================================================================
// launch
// =================================================================
extern "C" void kernel_launch(void* const* d_in, const int* in_sizes, int n_in,
                              void* d_out, int out_size)
{
    const float* x        = (const float*)d_in[0];
    const float* ve       = (const float*)d_in[1];
    const float* qkv_w    = (const float*)d_in[2];
    const float* lambdas  = (const float*)d_in[3];
    const float* c_proj_w = (const float*)d_in[4];
    float* out = (float*)d_out;

    float* qkv_p;
    cudaGetSymbolAddress((void**)&qkv_p, g_qkv);
    __nv_bfloat16 *xh, *xl, *wh, *wl, *yh, *yl, *ph, *pl;
    cudaGetSymbolAddress((void**)&xh, g_xh); cudaGetSymbolAddress((void**)&xl, g_xl);
    cudaGetSymbolAddress((void**)&wh, g_wh); cudaGetSymbolAddress((void**)&wl, g_wl);
    cudaGetSymbolAddress((void**)&yh, g_yh); cudaGetSymbolAddress((void**)&yl, g_yl);
    cudaGetSymbolAddress((void**)&ph, g_ph); cudaGetSymbolAddress((void**)&pl, g_pl);
    __nv_bfloat16 *qh, *ql, *kh, *kl, *vth, *vtl;
    cudaGetSymbolAddress((void**)&qh, g_qh); cudaGetSymbolAddress((void**)&ql, g_ql);
    cudaGetSymbolAddress((void**)&kh, g_kh); cudaGetSymbolAddress((void**)&kl, g_kl);
    cudaGetSymbolAddress((void**)&vth, g_vth); cudaGetSymbolAddress((void**)&vtl, g_vtl);

    cudaFuncSetAttribute(mma_gemm_pre, cudaFuncAttributeMaxDynamicSharedMemorySize, GEMM_SMEM);
    cudaFuncSetAttribute(flash_mma, cudaFuncAttributeMaxDynamicSharedMemorySize, FL_SMEM);

    // 0) pre-split fp32 -> bf16 hi/lo (x, qkv_w, c_proj_w in one launch)
    split3<<<(N_X + N_W + N_P) / 1024, 256>>>(x, xh, xl, qkv_w, wh, wl,
                                              c_proj_w, ph, pl);

    // 1) qkv = x @ qkv_w^T
    mma_gemm_pre<<<dim3(N_QKV / 128, MM / 128), 256, GEMM_SMEM>>>(
        xh, xl, wh, wl, qkv_p, MM, N_QKV, CC);

    // 2) fused v-mix + rmsnorm + rotary + V transpose
    postproc_fused<<<dim3(TT / 64, BB * HH), 256>>>(
        qkv_p, ve, lambdas, qh, ql, kh, kl, vth, vtl);

    // 3) tensor-core causal flash attention -> y bf16 hi/lo
    flash_mma<<<dim3(TT / 128, BB * HH), 256, FL_SMEM>>>(
        qh, ql, kh, kl, vth, vtl, yh, yl);

    // 4) out = y @ c_proj_w^T
    mma_gemm_pre<<<dim3(CC / 128, MM / 128), 256, GEMM_SMEM>>>(
        yh, yl, ph, pl, out, MM, CC, CC);
}

// round 15
// speedup vs baseline: 1.0369x; 1.0369x over previous
#include <cuda_runtime.h>
#include <cuda_bf16.h>
#include <math.h>
#include <stdint.h>

// Problem constants
#define BB 4
#define TT 2048
#define CC 1024
#define HH 16
#define DD 64
#define MM (BB * TT)         // 8192
#define N_QKV (3 * CC)       // 3072
#define ATTN_SCALE 0.12f
#define RMS_EPS 1e-6f
#define LOG2E 1.4426950408889634f

// ---------------- device scratch (allocation-free) ----------------
__device__ float g_qkv[(size_t)MM * N_QKV];          // (M, 3C)
__device__ __nv_bfloat16 g_xh[(size_t)MM * CC],     g_xl[(size_t)MM * CC];
__device__ __nv_bfloat16 g_wh[(size_t)N_QKV * CC],  g_wl[(size_t)N_QKV * CC];
__device__ __nv_bfloat16 g_yh[(size_t)MM * CC],     g_yl[(size_t)MM * CC];
__device__ __nv_bfloat16 g_ph[(size_t)CC * CC],     g_pl[(size_t)CC * CC];
#define AHD ((size_t)BB * HH * TT * DD)
__device__ __nv_bfloat16 g_qh[AHD], g_ql[AHD];
__device__ __nv_bfloat16 g_kh[AHD], g_kl[AHD];
__device__ __nv_bfloat16 g_vth[AHD], g_vtl[AHD];

// =================================================================
// common helpers
// =================================================================
__device__ __forceinline__ uint32_t smem_u32(const void* p) {
    uint32_t a;
    asm("{ .reg .u64 t; cvta.to.shared.u64 t, %1; cvt.u32.u64 %0, t; }"
        : "=r"(a) : "l"(p));
    return a;
}

__device__ __forceinline__ void mma16816(float* d, const uint32_t* a, const uint32_t* b) {
    asm volatile(
        "mma.sync.aligned.m16n8k16.row.col.f32.bf16.bf16.f32 "
        "{%0,%1,%2,%3}, {%4,%5,%6,%7}, {%8,%9}, {%0,%1,%2,%3};"
        : "+f"(d[0]), "+f"(d[1]), "+f"(d[2]), "+f"(d[3])
        : "r"(a[0]), "r"(a[1]), "r"(a[2]), "r"(a[3]), "r"(b[0]), "r"(b[1]));
}

#define LDSM_X4(r, addr) \
    asm volatile("ldmatrix.sync.aligned.m8n8.x4.shared.b16 {%0,%1,%2,%3}, [%4];" \
                 : "=r"((r)[0]), "=r"((r)[1]), "=r"((r)[2]), "=r"((r)[3]) : "r"(addr))

#define CP_ASYNC(dst, src) \
    asm volatile("cp.async.cg.shared.global [%0], [%1], 16;" \
                 :: "r"(dst), "l"(src) : "memory")
#define CP_COMMIT() asm volatile("cp.async.commit_group;" ::: "memory")
#define CP_WAIT1()  asm volatile("cp.async.wait_group 1;" ::: "memory")

// pack (lo, hi) floats into one bf16x2 word (round-to-nearest-even,
// identical bits to __float2bfloat16)
__device__ __forceinline__ uint32_t cvt_bf16x2(float lo, float hi) {
    uint32_t r;
    asm("cvt.rn.bf16x2.f32 %0, %1, %2;" : "=r"(r) : "f"(hi), "f"(lo));
    return r;
}

// split two floats into hi bf16x2 word + lo (residual) bf16x2 word
__device__ __forceinline__ void split_pack(float p0, float p1,
                                           uint32_t& hw, uint32_t& lw) {
    hw = cvt_bf16x2(p0, p1);
    float f0 = __uint_as_float(hw << 16);
    float f1 = __uint_as_float(hw & 0xffff0000u);
    lw = cvt_bf16x2(p0 - f0, p1 - f1);
}

__device__ __forceinline__ float ex2f(float x) {
    float y;
    asm("ex2.approx.f32 %0, %1;" : "=f"(y) : "f"(x));
    return y;
}

// =================================================================
// split3: one launch splits x, qkv_w, c_proj_w fp32 -> bf16 hi/lo
// =================================================================
__device__ __forceinline__ void split4(const float* __restrict__ in, int i,
                                       __nv_bfloat16* __restrict__ hi,
                                       __nv_bfloat16* __restrict__ lo)
{
    float4 f4 = *(const float4*)(in + i);
    uint32_t h0, l0, h1, l1;
    split_pack(f4.x, f4.y, h0, l0);
    split_pack(f4.z, f4.w, h1, l1);
    *(uint2*)(hi + i) = make_uint2(h0, h1);
    *(uint2*)(lo + i) = make_uint2(l0, l1);
}

#define N_X (MM * CC)
#define N_W (N_QKV * CC)
#define N_P (CC * CC)

__global__ __launch_bounds__(256)
void split3(const float* __restrict__ x,
            __nv_bfloat16* __restrict__ xh, __nv_bfloat16* __restrict__ xl,
            const float* __restrict__ w,
            __nv_bfloat16* __restrict__ wh, __nv_bfloat16* __restrict__ wl,
            const float* __restrict__ p,
            __nv_bfloat16* __restrict__ ph, __nv_bfloat16* __restrict__ pl)
{
    const int i = (blockIdx.x * 256 + threadIdx.x) * 4;
    if (i < N_X) {
        split4(x, i, xh, xl);
    } else if (i < N_X + N_W) {
        split4(w, i - N_X, wh, wl);
    } else {
        split4(p, i - N_X - N_W, ph, pl);
    }
}

// =================================================================
// mma.sync bf16x3 GEMM (pre-split, cp.async double buffer, ldmatrix;
// B fragments fetched with x4 ldmatrix). Unchanged from R11 winner.
// =================================================================
#define SROW 20
#define ARR_W (128 * SROW)
#define BUF_W (4 * ARR_W)
#define GEMM_SMEM (2 * BUF_W * 4)

__global__ __launch_bounds__(256, 2)
void mma_gemm_pre(const __nv_bfloat16* __restrict__ Ahg,
                  const __nv_bfloat16* __restrict__ Alg,
                  const __nv_bfloat16* __restrict__ Bhg,
                  const __nv_bfloat16* __restrict__ Blg,
                  float* __restrict__ C, int M, int N, int K)
{
    extern __shared__ uint32_t sw[];
    const uint32_t sbase = smem_u32(sw);

    const int tid = threadIdx.x;
    const int wid = tid >> 5;
    const int lane = tid & 31;
    const int g = lane >> 2;
    const int tig = lane & 3;
    const int wm = (wid & 1) * 64;
    const int wn = (wid >> 1) * 32;

    const int bm = blockIdx.y * 128;
    const int bn = blockIdx.x * 128;

    const int s0 = tid * 2;
    const int lrow0 = s0 >> 2, lseg0 = s0 & 3;
    const int lrow1 = (s0 + 1) >> 2, lseg1 = (s0 + 1) & 3;

    const uint32_t a16 = ((uint32_t)((wm + (lane & 15)) * SROW + (lane >> 4) * 4)) * 4;
    const uint32_t b8q = ((uint32_t)((wn + ((lane >> 4) << 3) + (lane & 7)) * SROW +
                                     ((lane >> 3) & 1) * 4)) * 4;

    float acc[4][4][4];
#pragma unroll
    for (int mt = 0; mt < 4; mt++)
#pragma unroll
        for (int nt = 0; nt < 4; nt++)
#pragma unroll
            for (int r = 0; r < 4; r++) acc[mt][nt][r] = 0.0f;

    const int nch = K >> 5;

    auto issue = [&](int ci, int buf) {
        const int kc = ci << 5;
        const uint32_t bb = sbase + buf * (BUF_W * 4);
#pragma unroll
        for (int j = 0; j < 2; j++) {
            const int row = j ? lrow1 : lrow0;
            const int seg = j ? lseg1 : lseg0;
            const size_t goff = (size_t)(bm + row) * K + kc + seg * 8;
            const size_t goffB = (size_t)(bn + row) * K + kc + seg * 8;
            const uint32_t soff = (row * SROW + seg * 4) * 4;
            CP_ASYNC(bb + 0 * ARR_W * 4 + soff, Ahg + goff);
            CP_ASYNC(bb + 1 * ARR_W * 4 + soff, Alg + goff);
            CP_ASYNC(bb + 2 * ARR_W * 4 + soff, Bhg + goffB);
            CP_ASYNC(bb + 3 * ARR_W * 4 + soff, Blg + goffB);
        }
    };

    issue(0, 0); CP_COMMIT();
    issue(1, 1); CP_COMMIT();

    for (int ci = 0; ci < nch; ci++) {
        const int buf = ci & 1;
        CP_WAIT1();
        __syncthreads();

        const uint32_t Ah_b = sbase + buf * (BUF_W * 4);
        const uint32_t Al_b = Ah_b + ARR_W * 4;
        const uint32_t Bh_b = Ah_b + 2 * ARR_W * 4;
        const uint32_t Bl_b = Ah_b + 3 * ARR_W * 4;

#pragma unroll
        for (int ks = 0; ks < 2; ks++) {
            const uint32_t kwb = ks * 32;
            uint32_t bhf[4][2], blf[4][2];
#pragma unroll
            for (int ntp = 0; ntp < 2; ntp++) {
                uint32_t q[4];
                LDSM_X4(q, Bh_b + b8q + ntp * (16 * SROW * 4) + kwb);
                bhf[2 * ntp][0] = q[0]; bhf[2 * ntp][1] = q[1];
                bhf[2 * ntp + 1][0] = q[2]; bhf[2 * ntp + 1][1] = q[3];
                LDSM_X4(q, Bl_b + b8q + ntp * (16 * SROW * 4) + kwb);
                blf[2 * ntp][0] = q[0]; blf[2 * ntp][1] = q[1];
                blf[2 * ntp + 1][0] = q[2]; blf[2 * ntp + 1][1] = q[3];
            }
#pragma unroll
            for (int mt = 0; mt < 4; mt++) {
                uint32_t ah[4], al[4];
                LDSM_X4(ah, Ah_b + a16 + mt * (16 * SROW * 4) + kwb);
                LDSM_X4(al, Al_b + a16 + mt * (16 * SROW * 4) + kwb);
#pragma unroll
                for (int nt = 0; nt < 4; nt++) {
                    mma16816(acc[mt][nt], ah, bhf[nt]);
                    mma16816(acc[mt][nt], ah, blf[nt]);
                    mma16816(acc[mt][nt], al, bhf[nt]);
                }
            }
        }
        __syncthreads();
        if (ci + 2 < nch) issue(ci + 2, buf);
        CP_COMMIT();
    }

#pragma unroll
    for (int mt = 0; mt < 4; mt++) {
        const int r0 = bm + wm + mt * 16 + g;
#pragma unroll
        for (int nt = 0; nt < 4; nt++) {
            const int col = bn + wn + nt * 8 + tig * 2;
            *(float2*)&C[(size_t)r0 * N + col] =
                make_float2(acc[mt][nt][0], acc[mt][nt][1]);
            *(float2*)&C[(size_t)(r0 + 8) * N + col] =
                make_float2(acc[mt][nt][2], acc[mt][nt][3]);
        }
    }
}

// =================================================================
// Fused post-process + V transpose (fast __sincosf + cvt packing).
// Grid (TT/64, B*H), 256 threads; thread (tr=tid>>2, tig=tid&3)
// owns row t=tr, d = tig*16..+15.
// =================================================================
__global__ __launch_bounds__(256)
void postproc_fused(const float* __restrict__ qkv, const float* __restrict__ ve,
                    const float* __restrict__ lambdas,
                    __nv_bfloat16* __restrict__ qh, __nv_bfloat16* __restrict__ ql,
                    __nv_bfloat16* __restrict__ kh, __nv_bfloat16* __restrict__ kl,
                    __nv_bfloat16* __restrict__ vth, __nv_bfloat16* __restrict__ vtl)
{
    __shared__ uint16_t svh[64][65], svl[64][65];

    const int tid = threadIdx.x;
    const int bh = blockIdx.y;
    const int tb = blockIdx.x;
    const int b = bh >> 4;
    const int h = bh & 15;
    const int tr = tid >> 2;
    const int tig = tid & 3;
    const int d0 = tig * 16;
    const int t = tb * 64 + tr;
    const int m = b * TT + t;

    const float* row = qkv + (size_t)m * N_QKV + h * DD;
    const float* verow = ve + (size_t)m * CC + h * DD;
    const float lam0 = lambdas[0], lam1 = lambdas[1];

    float q[16], k[16], v[16];
#pragma unroll
    for (int u = 0; u < 4; u++) {
        *(float4*)&q[4 * u] = *(const float4*)(row + d0 + 4 * u);
        *(float4*)&k[4 * u] = *(const float4*)(row + CC + d0 + 4 * u);
        float4 v4 = *(const float4*)(row + 2 * CC + d0 + 4 * u);
        float4 e4 = *(const float4*)(verow + d0 + 4 * u);
        v[4 * u + 0] = lam0 * v4.x + lam1 * e4.x;
        v[4 * u + 1] = lam0 * v4.y + lam1 * e4.y;
        v[4 * u + 2] = lam0 * v4.z + lam1 * e4.z;
        v[4 * u + 3] = lam0 * v4.w + lam1 * e4.w;
    }

    // rmsnorm over 64 d (16 per thread, reduce across tig group)
    float sq = 0.0f, sk = 0.0f;
#pragma unroll
    for (int j = 0; j < 16; j++) { sq += q[j] * q[j]; sk += k[j] * k[j]; }
    sq += __shfl_xor_sync(0xffffffffu, sq, 1);
    sq += __shfl_xor_sync(0xffffffffu, sq, 2);
    sk += __shfl_xor_sync(0xffffffffu, sk, 1);
    sk += __shfl_xor_sync(0xffffffffu, sk, 2);
    const float rq = 1.0f / sqrtf(sq * (1.0f / 64.0f) + RMS_EPS);
    const float rk = 1.0f / sqrtf(sk * (1.0f / 64.0f) + RMS_EPS);
#pragma unroll
    for (int j = 0; j < 16; j++) { q[j] *= rq; k[j] *= rk; }

    // rotary: partner exchange (d <-> d+32) via shfl_xor(2)
    float qp[16], kp[16];
#pragma unroll
    for (int j = 0; j < 16; j++) {
        qp[j] = __shfl_xor_sync(0xffffffffu, q[j], 2);
        kp[j] = __shfl_xor_sync(0xffffffffu, k[j], 2);
    }
    const float qs = ATTN_SCALE * LOG2E;
    const bool lowf = ((tig & 1) == 0);   // these 16 d's have nonzero freqs
    const bool x1side = (tig < 2);
#pragma unroll
    for (int j = 0; j < 16; j++) {
        float c = 1.0f, s = 0.0f;
        if (lowf) {
            const float ang = (float)exp2(-(10.0 / 15.0) * (double)j);
            __sincosf((float)t * ang, &s, &c);
        }
        float qn = x1side ? (q[j] * c + qp[j] * s) : (q[j] * c - qp[j] * s);
        float kn = x1side ? (k[j] * c + kp[j] * s) : (k[j] * c - kp[j] * s);
        q[j] = qn * qs;
        k[j] = kn;
    }

    // store q, k bf16 hi/lo (row-major (B*H, T, D))
    {
        const size_t o = ((size_t)bh * TT + t) * DD + d0;
        uint32_t qhw[8], qlw[8], khw[8], klw[8];
#pragma unroll
        for (int j = 0; j < 8; j++) {
            split_pack(q[2 * j], q[2 * j + 1], qhw[j], qlw[j]);
            split_pack(k[2 * j], k[2 * j + 1], khw[j], klw[j]);
        }
        *(uint4*)(qh + o) = make_uint4(qhw[0], qhw[1], qhw[2], qhw[3]);
        *(uint4*)(qh + o + 8) = make_uint4(qhw[4], qhw[5], qhw[6], qhw[7]);
        *(uint4*)(ql + o) = make_uint4(qlw[0], qlw[1], qlw[2], qlw[3]);
        *(uint4*)(ql + o + 8) = make_uint4(qlw[4], qlw[5], qlw[6], qlw[7]);
        *(uint4*)(kh + o) = make_uint4(khw[0], khw[1], khw[2], khw[3]);
        *(uint4*)(kh + o + 8) = make_uint4(khw[4], khw[5], khw[6], khw[7]);
        *(uint4*)(kl + o) = make_uint4(klw[0], klw[1], klw[2], klw[3]);
        *(uint4*)(kl + o + 8) = make_uint4(klw[4], klw[5], klw[6], klw[7]);
    }

    // stage v hi/lo into smem [t][d]
#pragma unroll
    for (int j = 0; j < 8; j++) {
        uint32_t hw, lw;
        split_pack(v[2 * j], v[2 * j + 1], hw, lw);
        svh[tr][d0 + 2 * j] = (uint16_t)(hw & 0xffff);
        svh[tr][d0 + 2 * j + 1] = (uint16_t)(hw >> 16);
        svl[tr][d0 + 2 * j] = (uint16_t)(lw & 0xffff);
        svl[tr][d0 + 2 * j + 1] = (uint16_t)(lw >> 16);
    }
    __syncthreads();

    // write V transposed: (B*H, D, T), coalesced along t
    {
        const int r = tid >> 2;          // d index
        const int cs = tig * 16;         // t chunk
        const size_t dst = ((size_t)bh * DD + r) * TT + tb * 64 + cs;
        uint32_t* oh = (uint32_t*)(vth + dst);
        uint32_t* ol = (uint32_t*)(vtl + dst);
#pragma unroll
        for (int j = 0; j < 8; j++) {
            oh[j] = (uint32_t)svh[cs + 2 * j][r] |
                    ((uint32_t)svh[cs + 2 * j + 1][r] << 16);
            ol[j] = (uint32_t)svl[cs + 2 * j][r] |
                    ((uint32_t)svl[cs + 2 * j + 1][r] << 16);
        }
    }
}

// =================================================================
// Tensor-core flash attention (causal, no-max softmax via ex2,
// bf16x3), register-resident P, register-cached Q fragments,
// uniform-branch causal mask, cvt.bf16x2 packing.
// BQ=128, BKV=64, 256 threads, 2 CTAs/SM (110.6 KB smem).
// =================================================================
#define FL_SROW 36
#define FLQ_H 0
#define FLQ_L 4608
#define FLKV 9216
#define FL_SMEM (27648 * 4)   // 110592 B

__global__ __launch_bounds__(256, 2)
void flash_mma(const __nv_bfloat16* __restrict__ qh, const __nv_bfloat16* __restrict__ ql,
               const __nv_bfloat16* __restrict__ kh, const __nv_bfloat16* __restrict__ kl,
               const __nv_bfloat16* __restrict__ vth, const __nv_bfloat16* __restrict__ vtl,
               __nv_bfloat16* __restrict__ yh, __nv_bfloat16* __restrict__ yl)
{
    extern __shared__ uint32_t sw[];
    const uint32_t sb = smem_u32(sw);
    const int tid = threadIdx.x;
    const int wid = tid >> 5;
    const int lane = tid & 31;
    const int g = lane >> 2;
    const int tig = lane & 3;
    const int bh = blockIdx.y;
    const int qb = (int)gridDim.x - 1 - (int)blockIdx.x;   // heavy first

    const int wm = wid * 16;    // this warp's 16 rows of the 128-row Q tile

    const uint32_t a16 = ((uint32_t)((lane & 15) * FL_SROW + (lane >> 4) * 4)) * 4;
    const uint32_t b8q = ((uint32_t)((((lane >> 4) << 3) + (lane & 7)) * FL_SROW +
                                     ((lane >> 3) & 1) * 4)) * 4;

    const size_t base = (size_t)bh * TT * DD;

    // ---- Q tile load (cp.async): 2 arrays x 128 rows ----
    {
        const int arr = tid >> 7;
        const int row = tid & 127;
        const __nv_bfloat16* src = (arr ? ql : qh) + base + ((size_t)(qb * 128 + row)) * 64;
        const uint32_t dst = sb + ((arr ? FLQ_L : FLQ_H) + row * FL_SROW) * 4;
#pragma unroll
        for (int s = 0; s < 8; s++) CP_ASYNC(dst + s * 16, src + s * 8);
    }

    // KV loader mapping: 4 arrays x 64 rows
    const int kvarr = tid >> 6;          // 0:Kh 1:Kl 2:Vth 3:Vtl
    const int kvrow = tid & 63;
    const bool kvisV = kvarr >= 2;
    const __nv_bfloat16* kvbase =
        (kvarr == 0) ? (kh + base) : (kvarr == 1) ? (kl + base)
        : (kvarr == 2) ? (vth + base) : (vtl + base);
    const uint32_t kvdst0 = sb + (FLKV + kvarr * 2304 + kvrow * FL_SROW) * 4;

    auto issueKV = [&](int kb, int buf) {
        const __nv_bfloat16* src = kvisV
            ? (kvbase + (size_t)kvrow * TT + kb * 64)
            : (kvbase + ((size_t)(kb * 64 + kvrow)) * 64);
        const uint32_t dst = kvdst0 + buf * 9216 * 4;
#pragma unroll
        for (int s = 0; s < 8; s++) CP_ASYNC(dst + s * 16, src + s * 8);
    };

    const int nkb = 2 * qb + 2;
    issueKV(0, 0); CP_COMMIT();          // group: Q + KV0
    if (nkb > 1) issueKV(1, 1);
    CP_COMMIT();
    CP_WAIT1();                          // Q + KV0 ready
    __syncthreads();

    // ---- cache Q fragments in registers (CTA-invariant) ----
    uint32_t qfh[4][4], qfl[4][4];
#pragma unroll
    for (int ks = 0; ks < 4; ks++) {
        LDSM_X4(qfh[ks], sb + FLQ_H * 4 + a16 + wm * (FL_SROW * 4) + ks * 32);
        LDSM_X4(qfl[ks], sb + FLQ_L * 4 + a16 + wm * (FL_SROW * 4) + ks * 32);
    }

    float O[8][4];
    float lp[2] = {0.0f, 0.0f};
#pragma unroll
    for (int nt = 0; nt < 8; nt++)
#pragma unroll
        for (int r = 0; r < 4; r++) O[nt][r] = 0.0f;

    for (int kb = 0; kb < nkb; kb++) {
        const int buf = kb & 1;
        const uint32_t Khb = sb + (FLKV + buf * 9216) * 4;
        const uint32_t Klb = Khb + 2304 * 4;
        const uint32_t Vhb = Khb + 4608 * 4;
        const uint32_t Vlb = Khb + 6912 * 4;

        // ---- S = Q K^T (bf16x3): 16 rows x 64 cols per warp ----
        float S[8][4];
#pragma unroll
        for (int nt = 0; nt < 8; nt++)
#pragma unroll
            for (int r = 0; r < 4; r++) S[nt][r] = 0.0f;

#pragma unroll
        for (int ks = 0; ks < 4; ks++) {
            const uint32_t kwb = ks * 32;
#pragma unroll
            for (int ntp = 0; ntp < 4; ntp++) {
                uint32_t qk[4], qkl[4];
                LDSM_X4(qk, Khb + b8q + ntp * (16 * FL_SROW * 4) + kwb);
                LDSM_X4(qkl, Klb + b8q + ntp * (16 * FL_SROW * 4) + kwb);
                uint32_t b0[2] = {qk[0], qk[1]}, b1[2] = {qk[2], qk[3]};
                uint32_t c0[2] = {qkl[0], qkl[1]}, c1[2] = {qkl[2], qkl[3]};
                mma16816(S[2 * ntp], qfh[ks], b0);
                mma16816(S[2 * ntp], qfh[ks], c0);
                mma16816(S[2 * ntp], qfl[ks], b0);
                mma16816(S[2 * ntp + 1], qfh[ks], b1);
                mma16816(S[2 * ntp + 1], qfh[ks], c1);
                mma16816(S[2 * ntp + 1], qfl[ks], b1);
            }
        }

        // ---- PV with fused exp2/pack (uniform-branch causal mask) ----
        const bool diag = (kb >= 2 * qb);
#pragma unroll
        for (int ks = 0; ks < 4; ks++) {
            const uint32_t kwb = ks * 32;
            uint32_t aph[4], apl[4];
            if (!diag) {
#pragma unroll
                for (int j = 0; j < 2; j++) {
                    const int nt = 2 * ks + j;
#pragma unroll
                    for (int h2 = 0; h2 < 2; h2++) {
                        float p0 = ex2f(S[nt][h2 * 2 + 0]);
                        float p1 = ex2f(S[nt][h2 * 2 + 1]);
                        lp[h2] += p0 + p1;
                        split_pack(p0, p1, aph[j * 2 + h2], apl[j * 2 + h2]);
                    }
                }
            } else {
#pragma unroll
                for (int j = 0; j < 2; j++) {
                    const int nt = 2 * ks + j;
                    const int c0i = kb * 64 + nt * 8 + tig * 2;
#pragma unroll
                    for (int h2 = 0; h2 < 2; h2++) {
                        const int grow = qb * 128 + wm + g + h2 * 8;
                        float p0 = (c0i > grow) ? 0.0f : ex2f(S[nt][h2 * 2 + 0]);
                        float p1 = (c0i + 1 > grow) ? 0.0f : ex2f(S[nt][h2 * 2 + 1]);
                        lp[h2] += p0 + p1;
                        split_pack(p0, p1, aph[j * 2 + h2], apl[j * 2 + h2]);
                    }
                }
            }
#pragma unroll
            for (int ntp = 0; ntp < 4; ntp++) {
                uint32_t qv[4], qvl[4];
                LDSM_X4(qv, Vhb + b8q + ntp * (16 * FL_SROW * 4) + kwb);
                LDSM_X4(qvl, Vlb + b8q + ntp * (16 * FL_SROW * 4) + kwb);
                uint32_t b0[2] = {qv[0], qv[1]}, b1[2] = {qv[2], qv[3]};
                uint32_t c0[2] = {qvl[0], qvl[1]}, c1[2] = {qvl[2], qvl[3]};
                mma16816(O[2 * ntp], aph, b0);
                mma16816(O[2 * ntp], aph, c0);
                mma16816(O[2 * ntp], apl, b0);
                mma16816(O[2 * ntp + 1], aph, b1);
                mma16816(O[2 * ntp + 1], aph, c1);
                mma16816(O[2 * ntp + 1], apl, b1);
            }
        }
        __syncthreads();                 // all warps done reading buf
        if (kb + 2 < nkb) issueKV(kb + 2, buf);
        CP_COMMIT();
        CP_WAIT1();                      // tile kb+1 ready
        __syncthreads();
    }

    // ---- row-sum reduce (warp-local) ----
#pragma unroll
    for (int i = 0; i < 2; i++) {
        lp[i] += __shfl_xor_sync(0xffffffffu, lp[i], 1);
        lp[i] += __shfl_xor_sync(0xffffffffu, lp[i], 2);
    }

    // ---- epilogue: O/l -> y bf16 hi/lo, (M, C) layout ----
    const int b = bh >> 4;
    const int h = bh & 15;
#pragma unroll
    for (int h2 = 0; h2 < 2; h2++) {
        const float linv = 1.0f / lp[h2];
        const int t = qb * 128 + wm + g + h2 * 8;
        const size_t rowoff = ((size_t)(b * TT + t)) * CC + h * 64;
#pragma unroll
        for (int nt = 0; nt < 8; nt++) {
            float o0 = O[nt][h2 * 2 + 0] * linv;
            float o1 = O[nt][h2 * 2 + 1] * linv;
            uint32_t hw, lw;
            split_pack(o0, o1, hw, lw);
            const size_t col = rowoff + nt * 8 + tig * 2;
            *(uint32_t*)(yh + col) = hw;
            *(uint32_t*)(yl + col) = lw;
        }
    }
}

// =================================================================
// launch
// =================================================================
extern "C" void kernel_launch(void* const* d_in, const int* in_sizes, int n_in,
                              void* d_out, int out_size)
{
    const float* x        = (const float*)d_in[0];
    const float* ve       = (const float*)d_in[1];
    const float* qkv_w    = (const float*)d_in[2];
    const float* lambdas  = (const float*)d_in[3];
    const float* c_proj_w = (const float*)d_in[4];
    float* out = (float*)d_out;

    float* qkv_p;
    cudaGetSymbolAddress((void**)&qkv_p, g_qkv);
    __nv_bfloat16 *xh, *xl, *wh, *wl, *yh, *yl, *ph, *pl;
    cudaGetSymbolAddress((void**)&xh, g_xh); cudaGetSymbolAddress((void**)&xl, g_xl);
    cudaGetSymbolAddress((void**)&wh, g_wh); cudaGetSymbolAddress((void**)&wl, g_wl);
    cudaGetSymbolAddress((void**)&yh, g_yh); cudaGetSymbolAddress((void**)&yl, g_yl);
    cudaGetSymbolAddress((void**)&ph, g_ph); cudaGetSymbolAddress((void**)&pl, g_pl);
    __nv_bfloat16 *qh, *ql, *kh, *kl, *vth, *vtl;
    cudaGetSymbolAddress((void**)&qh, g_qh); cudaGetSymbolAddress((void**)&ql, g_ql);
    cudaGetSymbolAddress((void**)&kh, g_kh); cudaGetSymbolAddress((void**)&kl, g_kl);
    cudaGetSymbolAddress((void**)&vth, g_vth); cudaGetSymbolAddress((void**)&vtl, g_vtl);

    cudaFuncSetAttribute(mma_gemm_pre, cudaFuncAttributeMaxDynamicSharedMemorySize, GEMM_SMEM);
    cudaFuncSetAttribute(flash_mma, cudaFuncAttributeMaxDynamicSharedMemorySize, FL_SMEM);

    // 0) pre-split fp32 -> bf16 hi/lo (x, qkv_w, c_proj_w in one launch)
    split3<<<(N_X + N_W + N_P) / 1024, 256>>>(x, xh, xl, qkv_w, wh, wl,
                                              c_proj_w, ph, pl);

    // 1) qkv = x @ qkv_w^T
    mma_gemm_pre<<<dim3(N_QKV / 128, MM / 128), 256, GEMM_SMEM>>>(
        xh, xl, wh, wl, qkv_p, MM, N_QKV, CC);

    // 2) fused v-mix + rmsnorm + rotary + V transpose
    postproc_fused<<<dim3(TT / 64, BB * HH), 256>>>(
        qkv_p, ve, lambdas, qh, ql, kh, kl, vth, vtl);

    // 3) tensor-core causal flash attention -> y bf16 hi/lo
    flash_mma<<<dim3(TT / 128, BB * HH), 256, FL_SMEM>>>(
        qh, ql, kh, kl, vth, vtl, yh, yl);

    // 4) out = y @ c_proj_w^T
    mma_gemm_pre<<<dim3(CC / 128, MM / 128), 256, GEMM_SMEM>>>(
        yh, yl, ph, pl, out, MM, CC, CC);
}